// round 14
// baseline (speedup 1.0000x reference)
#include <cuda_runtime.h>
#include <math.h>

#define B_SI 4.1491f
#define B_O  5.803f
#define CUTOFF 3.5f
#define PI_F 3.14159274101257324f   // (float)M_PI

#define CDIM   8
#define NCELLS 512                  // CDIM^3
#define CCAP   32                   // fixed capacity per cell
#define NMAX   8192

// ---------------- f32x2 packed helpers (sm_100+) -----------------------------------
#define PK2(out, lo, hi) asm("mov.b64 %0, {%1, %2};" : "=l"(out) : "f"(lo), "f"(hi))
#define UNPK2(lo, hi, in) asm("mov.b64 {%0, %1}, %2;" : "=f"(lo), "=f"(hi) : "l"(in))
#define ADD2(d, a, b) asm("add.rn.f32x2 %0, %1, %2;" : "=l"(d) : "l"(a), "l"(b))
#define MUL2(d, a, b) asm("mul.rn.f32x2 %0, %1, %2;" : "=l"(d) : "l"(a), "l"(b))
#define FMA2(d, a, b, c) asm("fma.rn.f32x2 %0, %1, %2, %3;" : "=l"(d) : "l"(a), "l"(b), "l"(c))

// ---------------- device globals (scratch; no allocations allowed) ----------------
__device__ float  g_inv[9];
__device__ float  g_cellm[9];
__device__ float  g_rho, g_r0, g_dr, g_rsafe;
__device__ int    g_cellokGeom;
__device__ double g_hist[256];        // zero at start; re-zeroed by final_kernel
__device__ double g_qsum, g_vfsum;    // same invariant
__device__ int    g_arriveF, g_nSiTot, g_overflow;

__device__ float4 g_fracA[NMAX];                 // per ORIGINAL atom: wrapped frac + b
__device__ float4 g_scart[NCELLS * CCAP];        // slotted cartesian (wrapped) + b
__device__ int    g_sorig[NCELLS * CCAP];
__device__ int    g_cellCnt[NCELLS];             // zero at start; re-zeroed by final

// ---------------- helpers ----------------------------------------------------------
__device__ __forceinline__ void insert4(float bd2[4], int bj[4], float dd, int jj) {
    if (dd < bd2[3]) {
        #pragma unroll
        for (int k = 0; k < 4; k++) {
            if (dd < bd2[k]) {
                float td = bd2[k]; bd2[k] = dd; dd = td;
                int   tj = bj[k];  bj[k]  = jj; jj = tj;
            }
        }
    }
}

__device__ __forceinline__ void warp_merge_top4(float bd2[4], int bj[4], int lane,
                                                float seld2[4], int selj[4]) {
    const float INF = 3.402823466e38f;
    int ptr = 0;
    #pragma unroll
    for (int r = 0; r < 4; r++) {
        float mv = (ptr < 4) ? bd2[ptr] : INF;
        int   mj = (ptr < 4) ? bj[ptr]  : 0x7fffffff;
        int   ml = lane;
        #pragma unroll
        for (int o = 16; o > 0; o >>= 1) {
            float ov = __shfl_down_sync(0xffffffffu, mv, o);
            int   oj = __shfl_down_sync(0xffffffffu, mj, o);
            int   ol = __shfl_down_sync(0xffffffffu, ml, o);
            if (ov < mv || (ov == mv && oj < mj)) { mv = ov; mj = oj; ml = ol; }
        }
        mv = __shfl_sync(0xffffffffu, mv, 0);
        mj = __shfl_sync(0xffffffffu, mj, 0);
        ml = __shfl_sync(0xffffffffu, ml, 0);
        if (lane == ml) ptr++;
        seld2[r] = mv; selj[r] = mj;
    }
}

__device__ __forceinline__ void compute_inv(const float a[9], float iv[9], float* det_out) {
    float c00 = a[4]*a[8] - a[5]*a[7];
    float c01 = a[5]*a[6] - a[3]*a[8];
    float c02 = a[3]*a[7] - a[4]*a[6];
    float det = a[0]*c00 + a[1]*c01 + a[2]*c02;
    float id  = 1.0f / det;
    iv[0] = c00*id;  iv[3] = c01*id;  iv[6] = c02*id;
    iv[1] = (a[2]*a[7] - a[1]*a[8])*id;
    iv[4] = (a[0]*a[8] - a[2]*a[6])*id;
    iv[7] = (a[1]*a[6] - a[0]*a[7])*id;
    iv[2] = (a[1]*a[5] - a[2]*a[4])*id;
    iv[5] = (a[2]*a[3] - a[0]*a[5])*id;
    iv[8] = (a[0]*a[4] - a[1]*a[3])*id;
    *det_out = det;
}

// ---------------- assign: straight-line frac + direct slotted scatter (no syncs) ----
__global__ void __launch_bounds__(128)
assign_kernel(const float* __restrict__ pos, const float* __restrict__ cell,
              const float* __restrict__ rbins, const int* __restrict__ species,
              int n, int nbins) {
    int t = threadIdx.x;
    int i = blockIdx.x * 128 + t;

    // every thread computes the inverse redundantly (no shared, no syncs)
    float a[9], iv[9], det;
    #pragma unroll
    for (int k = 0; k < 9; k++) a[k] = cell[k];
    compute_inv(a, iv, &det);

    // block 0 / t0: geometric scalar prep (independent of atom pass)
    if (blockIdx.x == 0 && t == 0) {
        #pragma unroll
        for (int k = 0; k < 9; k++) { g_cellm[k] = a[k]; g_inv[k] = iv[k]; }
        float adet = fabsf(det);
        g_rho = (float)n / adet;
        float r0 = rbins[0], dr = rbins[1] - rbins[0];
        g_r0 = r0; g_dr = dr;
        float c00 = a[4]*a[8]-a[5]*a[7], c10 = a[5]*a[6]-a[3]*a[8], c20 = a[3]*a[7]-a[4]*a[6];
        float n1 = sqrtf(c00*c00 + c10*c10 + c20*c20);
        float x31x = a[7]*a[2]-a[8]*a[1], x31y = a[8]*a[0]-a[6]*a[2], x31z = a[6]*a[1]-a[7]*a[0];
        float n2 = sqrtf(x31x*x31x + x31y*x31y + x31z*x31z);
        float x12x = a[1]*a[5]-a[2]*a[4], x12y = a[2]*a[3]-a[0]*a[5], x12z = a[0]*a[4]-a[1]*a[3];
        float n3 = sqrtf(x12x*x12x + x12y*x12y + x12z*x12z);
        float pmin = fminf(adet/n1, fminf(adet/n2, adet/n3));
        float rmax = r0 + (float)(nbins - 1) * dr;
        g_cellokGeom = (rmax * (float)CDIM * 0.5f <= pmin) ? 1 : 0;
        g_rsafe = pmin / (float)CDIM;
    }

    int isSi = 0;
    if (i < n) {
        float px = pos[3*i], py = pos[3*i+1], pz = pos[3*i+2];
        float fx = px*iv[0] + py*iv[3] + pz*iv[6];
        float fy = px*iv[1] + py*iv[4] + pz*iv[7];
        float fz = px*iv[2] + py*iv[5] + pz*iv[8];
        fx -= floorf(fx); fy -= floorf(fy); fz -= floorf(fz);
        int cx = min((int)(fx * (float)CDIM), CDIM - 1);
        int cy = min((int)(fy * (float)CDIM), CDIM - 1);
        int cz = min((int)(fz * (float)CDIM), CDIM - 1);
        int c  = cx | (cy << 3) | (cz << 6);
        isSi = (species[i] == 0);
        float b = isSi ? B_SI : B_O;
        float4 fr; fr.x = fx; fr.y = fy; fr.z = fz; fr.w = b;
        g_fracA[i] = fr;                    // qtet + brute-path copy
        int rank = atomicAdd(&g_cellCnt[c], 1);
        if (rank < CCAP) {
            int s = c * CCAP + rank;
            float4 cc;
            cc.x = fr.x*a[0] + fr.y*a[3] + fr.z*a[6];
            cc.y = fr.x*a[1] + fr.y*a[4] + fr.z*a[7];
            cc.z = fr.x*a[2] + fr.y*a[5] + fr.z*a[8];
            cc.w = b;
            g_scart[s] = cc;
            g_sorig[s] = i;
        } else {
            atomicExch(&g_overflow, 1);     // degenerate density -> brute path
        }
    }
    // warp-level Si count (no shared, no block sync)
    int wcnt = __reduce_add_sync(0xffffffffu, isSi);
    if ((t & 31) == 0 && wcnt > 0) atomicAdd(&g_nSiTot, wcnt);
}

// ---------------- main: pair histogram (bx < pairBlocks) + qtet (rest) -------------
__global__ void __launch_bounds__(256, 5)
main_kernel(const float* __restrict__ pos, const int* __restrict__ species,
            int n, int nbins, int pairBlocks) {
    int bx = blockIdx.x;
    int t  = threadIdx.x;

    if (bx < pairBlocks) {
        // ===================== pair histogram =====================
        const int cellok = g_cellokGeom && !g_overflow;
        if (cellok && bx >= NCELLS) return;

        __shared__ unsigned long long scx[128], scy[128], scz[128];
        __shared__ float  scw[256];
        __shared__ float4 sjn[512];
        __shared__ float  shist[256];
        __shared__ int    nbS[63], nbCnt[63];
        __shared__ int    nbCum[64];
        __shared__ float  shx[63], shy[63], shz[63];

        shist[t] = 0.0f;

        const float r0 = g_r0, dr = g_dr;
        const float rmax  = r0 + (float)(nbins - 1) * dr;
        const float d2max = rmax * rmax + 0.01f;
        const float invdr = 1.0f / dr;
        const float binoff = -r0 * invdr;

        if (cellok) {
            int c  = bx;
            int cx = c & 7, cy = (c >> 3) & 7, cz = c >> 6;
            if (t < 63) {
                int tt = 62 + t;                    // t=0 -> self, t>0 -> positive half
                int ox = tt % 5 - 2, oy = (tt / 5) % 5 - 2, oz = tt / 25 - 2;
                int ucx = cx + ox, ucy = cy + oy, ucz = cz + oz;
                int nc = (ucx & 7) | ((ucy & 7) << 3) | ((ucz & 7) << 6);
                nbS[t]   = nc * CCAP;
                nbCnt[t] = g_cellCnt[nc];
                float wx = (float)((ucx < 0) ? -1 : (ucx >= CDIM ? 1 : 0));
                float wy = (float)((ucy < 0) ? -1 : (ucy >= CDIM ? 1 : 0));
                float wz = (float)((ucz < 0) ? -1 : (ucz >= CDIM ? 1 : 0));
                shx[t] = wx*g_cellm[0] + wy*g_cellm[3] + wz*g_cellm[6];
                shy[t] = wx*g_cellm[1] + wy*g_cellm[4] + wz*g_cellm[7];
                shz[t] = wx*g_cellm[2] + wy*g_cellm[5] + wz*g_cellm[8];
            }
            __syncthreads();
            // warp-shuffle exclusive scan over 63 counts (lane k -> cells 2k, 2k+1)
            if (t < 32) {
                int a  = nbCnt[2*t];
                int bb = (2*t + 1 < 63) ? nbCnt[2*t + 1] : 0;
                int s  = a + bb;
                int v  = s;
                #pragma unroll
                for (int o = 1; o < 32; o <<= 1) {
                    int u = __shfl_up_sync(0xffffffffu, v, o);
                    if (t >= o) v += u;
                }
                int ex = v - s;
                nbCum[2*t] = ex;
                if (2*t + 1 < 63) nbCum[2*t + 1] = ex + a;
                if (t == 31) nbCum[63] = ex + a;    // total
            }
            __syncthreads();
            int total     = nbCum[63];
            int selfStart = nbS[0];
            int nC        = nbCnt[0];              // self count
            int nCp       = (nC + 1) >> 1;

            // stage centers as packed SoA (pad odd with far sentinel, weight 0)
            for (int p = t; p < nCp; p += 256) {
                float4 a = g_scart[selfStart + 2*p];
                float4 bb;
                if (2*p + 1 < nC) bb = g_scart[selfStart + 2*p + 1];
                else { bb.x = 1e9f; bb.y = 1e9f; bb.z = 1e9f; bb.w = 0.0f; }
                unsigned long long ux, uy, uz;
                PK2(ux, a.x, bb.x); PK2(uy, a.y, bb.y); PK2(uz, a.z, bb.z);
                scx[p] = ux; scy[p] = uy; scz[p] = uz;
                scw[2*p]     = 2.0f * a.w;
                scw[2*p + 1] = 2.0f * bb.w;
            }
            __syncthreads();

            // ---- self-cell triangle (scalar, tiny) ----
            int npairs = nC * (nC - 1) / 2;
            for (int idx = t; idx < npairs; idx += 256) {
                int gj = (int)((1.0f + sqrtf(1.0f + 8.0f * (float)idx)) * 0.5f);
                while (gj * (gj - 1) / 2 > idx) gj--;
                while ((gj + 1) * gj / 2 <= idx) gj++;
                int ii = idx - gj * (gj - 1) / 2;
                float4 pi = g_scart[selfStart + ii];
                float4 pj = g_scart[selfStart + gj];
                float dx = pi.x - pj.x, dy = pi.y - pj.y, dz = pi.z - pj.z;
                float d2 = dx*dx + dy*dy + dz*dz;
                if (d2 < d2max) {
                    float dist;
                    asm("sqrt.approx.f32 %0, %1;" : "=f"(dist) : "f"(d2));
                    float x  = fmaf(dist, invdr, binoff);
                    int   b0 = __float2int_rd(x);
                    if ((unsigned)b0 < (unsigned)(nbins - 1)) {
                        float f = x - (float)b0;
                        float w = 2.0f * pi.w * pj.w;
                        atomicAdd(&shist[b0],     w * (1.0f - f));
                        atomicAdd(&shist[b0 + 1], w * f);
                    }
                }
            }

            // ---- main loop: centers (packed) vs 62 half-neighborhood cells ----
            for (int base = nC; base < total; base += 512) {
                int lim = min(512, total - base);
                // stage chunk of neighborhood NEGATED with wrap shifts applied
                for (int k = t; k < lim; k += 256) {
                    int gj = base + k;
                    int lo = 0;
                    if (nbCum[lo + 32] <= gj) lo += 32;
                    if (nbCum[lo + 16] <= gj) lo += 16;
                    if (nbCum[lo +  8] <= gj) lo +=  8;
                    if (nbCum[lo +  4] <= gj) lo +=  4;
                    if (nbCum[lo +  2] <= gj) lo +=  2;
                    if (nbCum[lo +  1] <= gj) lo +=  1;
                    float4 p = g_scart[nbS[lo] + (gj - nbCum[lo])];
                    float4 q;
                    q.x = -(p.x + shx[lo]);
                    q.y = -(p.y + shy[lo]);
                    q.z = -(p.z + shz[lo]);
                    q.w = p.w;
                    sjn[k] = q;
                }
                __syncthreads();
                for (int k = t; k < lim; k += 256) {
                    float4 pj = sjn[k];
                    unsigned long long px2, py2, pz2;
                    PK2(px2, pj.x, pj.x);
                    PK2(py2, pj.y, pj.y);
                    PK2(pz2, pj.z, pj.z);
                    float pjw = pj.w;
                    #pragma unroll 2
                    for (int p = 0; p < nCp; p++) {
                        unsigned long long dx2, dy2, dz2, d2p;
                        ADD2(dx2, scx[p], px2);      // cen + (-pj) = cen - pj
                        ADD2(dy2, scy[p], py2);
                        ADD2(dz2, scz[p], pz2);
                        MUL2(d2p, dz2, dz2);
                        FMA2(d2p, dy2, dy2, d2p);
                        FMA2(d2p, dx2, dx2, d2p);
                        float d2lo, d2hi;
                        UNPK2(d2lo, d2hi, d2p);
                        if (d2lo < d2max) {
                            float dist;
                            asm("sqrt.approx.f32 %0, %1;" : "=f"(dist) : "f"(d2lo));
                            float x  = fmaf(dist, invdr, binoff);
                            int   b0 = __float2int_rd(x);
                            if ((unsigned)b0 < (unsigned)(nbins - 1)) {
                                float f = x - (float)b0;
                                float w = scw[2*p] * pjw;
                                atomicAdd(&shist[b0],     w * (1.0f - f));
                                atomicAdd(&shist[b0 + 1], w * f);
                            }
                        }
                        if (d2hi < d2max) {
                            float dist;
                            asm("sqrt.approx.f32 %0, %1;" : "=f"(dist) : "f"(d2hi));
                            float x  = fmaf(dist, invdr, binoff);
                            int   b0 = __float2int_rd(x);
                            if ((unsigned)b0 < (unsigned)(nbins - 1)) {
                                float f = x - (float)b0;
                                float w = scw[2*p + 1] * pjw;
                                atomicAdd(&shist[b0],     w * (1.0f - f));
                                atomicAdd(&shist[b0 + 1], w * f);
                            }
                        }
                    }
                }
                __syncthreads();
            }
        } else {
            // ---- brute fallback (general cells / degenerate) ----
            int tilesJ = (n + 511) >> 9;
            int ib = bx / tilesJ;
            int jb = bx % tilesJ;
            int iBase = ib * 256, jBase = jb * 512;
            const float c0 = g_cellm[0], c1 = g_cellm[1], c2 = g_cellm[2];
            const float c3 = g_cellm[3], c4 = g_cellm[4], c5 = g_cellm[5];
            const float c6 = g_cellm[6], c7 = g_cellm[7], c8 = g_cellm[8];
            if (iBase < n && jBase + 511 > iBase) {
                for (int k = t; k < 512; k += 256) {
                    int j = jBase + k;
                    float4 v;
                    if (j < n) v = g_fracA[j];
                    else { v.x = 1e18f; v.y = 1e18f; v.z = 1e18f; v.w = 0.0f; }
                    sjn[k] = v;
                }
                __syncthreads();
                int i = iBase + t;
                if (i < n) {
                    float4 pi = g_fracA[i];
                    int kmin = i - jBase + 1; if (kmin < 0) kmin = 0;
                    int kmax = n - jBase; if (kmax > 512) kmax = 512;
                    for (int k = kmin; k < kmax; k++) {
                        float4 pj = sjn[k];
                        float fx = pi.x - pj.x; fx -= rintf(fx);
                        float fy = pi.y - pj.y; fy -= rintf(fy);
                        float fz = pi.z - pj.z; fz -= rintf(fz);
                        float dx = fx*c0 + fy*c3 + fz*c6;
                        float dy = fx*c1 + fy*c4 + fz*c7;
                        float dz = fx*c2 + fy*c5 + fz*c8;
                        float d2 = dx*dx + dy*dy + dz*dz;
                        if (d2 < d2max) {
                            float dist = sqrtf(d2);
                            float x  = fmaf(dist, invdr, binoff);
                            int   b0 = __float2int_rd(x);
                            if ((unsigned)b0 < (unsigned)(nbins - 1)) {
                                float f = x - (float)b0;
                                float w = 2.0f * pi.w * pj.w;
                                atomicAdd(&shist[b0],     w * (1.0f - f));
                                atomicAdd(&shist[b0 + 1], w * f);
                            }
                        }
                    }
                }
                __syncthreads();
            }
        }
        __syncthreads();
        if (t < nbins && shist[t] != 0.0f) atomicAdd(&g_hist[t], (double)shist[t]);
    } else {
        // ===================== tetrahedral order parameter =====================
        int qb   = bx - pairBlocks;
        int gw   = qb * 8 + (t >> 5);       // ORIGINAL atom index
        int lane = t & 31;
        int wib  = t >> 5;

        const float i0v = g_inv[0], i1v = g_inv[1], i2v = g_inv[2];
        const float i3v = g_inv[3], i4v = g_inv[4], i5v = g_inv[5];
        const float i6v = g_inv[6], i7v = g_inv[7], i8v = g_inv[8];
        const float c0 = g_cellm[0], c1 = g_cellm[1], c2 = g_cellm[2];
        const float c3 = g_cellm[3], c4 = g_cellm[4], c5 = g_cellm[5];
        const float c6 = g_cellm[6], c7 = g_cellm[7], c8 = g_cellm[8];
        const float rsafe  = g_rsafe;
        const int   cellok = g_cellokGeom && !g_overflow;
        const float INF = 3.402823466e38f;

        float qi = 0.0f;
        int   vf = 0;

        int i = -1, ccell = -1;
        float4 ci = {0.f, 0.f, 0.f, 0.f};
        if (gw < n) {
            if (cellok) {
                float4 fr = g_fracA[gw];
                if (fr.w == B_SI) {
                    i = gw;
                    int cx = min((int)(fr.x * (float)CDIM), CDIM - 1);
                    int cy = min((int)(fr.y * (float)CDIM), CDIM - 1);
                    int cz = min((int)(fr.z * (float)CDIM), CDIM - 1);
                    ccell = cx | (cy << 3) | (cz << 6);
                    ci.x = fr.x*c0 + fr.y*c3 + fr.z*c6;
                    ci.y = fr.x*c1 + fr.y*c4 + fr.z*c7;
                    ci.z = fr.x*c2 + fr.y*c5 + fr.z*c8;
                    ci.w = fr.w;
                }
            } else {
                if (species[gw] == 0) i = gw;
            }
        }

        if (i >= 0) {
            float pix = pos[3*i], piy = pos[3*i+1], piz = pos[3*i+2];
            float seld2[4]; int selj[4];
            bool valid = false;

            if (cellok) {
                int cx = ccell & 7, cy = (ccell >> 3) & 7, cz = ccell >> 6;
                float bd2[4] = {INF, INF, INF, INF};
                int   bj [4] = {0x7fffffff, 0x7fffffff, 0x7fffffff, 0x7fffffff};
                int found = 0;
                if (lane < 27) {
                    int ox = lane % 3 - 1, oy = (lane / 3) % 3 - 1, oz = lane / 9 - 1;
                    int ucx = cx + ox, ucy = cy + oy, ucz = cz + oz;
                    int nc = (ucx & 7) | ((ucy & 7) << 3) | ((ucz & 7) << 6);
                    float wx = (float)((ucx < 0) ? -1 : (ucx >= CDIM ? 1 : 0));
                    float wy = (float)((ucy < 0) ? -1 : (ucy >= CDIM ? 1 : 0));
                    float wz = (float)((ucz < 0) ? -1 : (ucz >= CDIM ? 1 : 0));
                    float sx = wx*c0 + wy*c3 + wz*c6;
                    float sy = wx*c1 + wy*c4 + wz*c7;
                    float sz = wx*c2 + wy*c5 + wz*c8;
                    int st = nc * CCAP, en = st + g_cellCnt[nc];
                    for (int s = st; s < en; s++) {
                        float4 fj = g_scart[s];
                        int jo = g_sorig[s];
                        if (fj.w == B_SI || jo == i) continue;
                        float dx = ci.x - (fj.x + sx);
                        float dy = ci.y - (fj.y + sy);
                        float dz = ci.z - (fj.z + sz);
                        float d2 = dx*dx + dy*dy + dz*dz;
                        found++;
                        insert4(bd2, bj, d2, jo);
                    }
                }
                int foundTot = __reduce_add_sync(0xffffffffu, found);
                warp_merge_top4(bd2, bj, lane, seld2, selj);
                valid = (foundTot >= 4) && (seld2[3] < rsafe * rsafe);
            }

            if (!valid) {
                // exact full-scan fallback
                float bd2[4] = {INF, INF, INF, INF};
                int   bj [4] = {0x7fffffff, 0x7fffffff, 0x7fffffff, 0x7fffffff};
                for (int j = lane; j < n; j += 32) {
                    if (j == i || species[j] == 0) continue;
                    float dx0 = pix - pos[3*j];
                    float dy0 = piy - pos[3*j+1];
                    float dz0 = piz - pos[3*j+2];
                    float fx = dx0*i0v + dy0*i3v + dz0*i6v;
                    float fy = dx0*i1v + dy0*i4v + dz0*i7v;
                    float fz = dx0*i2v + dy0*i5v + dz0*i8v;
                    fx -= rintf(fx); fy -= rintf(fy); fz -= rintf(fz);
                    float dx = fx*c0 + fy*c3 + fz*c6;
                    float dy = fx*c1 + fy*c4 + fz*c7;
                    float dz = fx*c2 + fy*c5 + fz*c8;
                    float d2 = dx*dx + dy*dy + dz*dz;
                    insert4(bd2, bj, d2, j);
                }
                warp_merge_top4(bd2, bj, lane, seld2, selj);
            }

            if (lane == 0 && selj[3] < n) {
                float ux[4], uy[4], uz[4], dmax = 0.0f;
                #pragma unroll
                for (int k = 0; k < 4; k++) {
                    int j = selj[k];
                    float dx0 = pix - pos[3*j];
                    float dy0 = piy - pos[3*j+1];
                    float dz0 = piz - pos[3*j+2];
                    float fx = dx0*i0v + dy0*i3v + dz0*i6v;
                    float fy = dx0*i1v + dy0*i4v + dz0*i7v;
                    float fz = dx0*i2v + dy0*i5v + dz0*i8v;
                    fx -= rintf(fx); fy -= rintf(fy); fz -= rintf(fz);
                    float dx = fx*c0 + fy*c3 + fz*c6;
                    float dy = fx*c1 + fy*c4 + fz*c7;
                    float dz = fx*c2 + fy*c5 + fz*c8;
                    float dist = sqrtf(seld2[k]);
                    dmax = fmaxf(dmax, dist);
                    ux[k] = dx / dist; uy[k] = dy / dist; uz[k] = dz / dist;
                }
                float s = 0.0f;
                #pragma unroll
                for (int k = 0; k < 4; k++)
                    #pragma unroll
                    for (int l = k + 1; l < 4; l++) {
                        float cc = ux[k]*ux[l] + uy[k]*uy[l] + uz[k]*uz[l];
                        float tt = cc + (1.0f / 3.0f);
                        s += tt * tt;
                    }
                if (dmax < CUTOFF) { qi = 1.0f - 0.375f * s; vf = 1; }
            }
        }

        __shared__ double s_q[8];
        __shared__ int    s_v[8];
        if (lane == 0) { s_q[wib] = (double)qi; s_v[wib] = vf; }
        __syncthreads();
        if (t == 0) {
            double qs = 0.0; int vs = 0;
            #pragma unroll
            for (int k = 0; k < 8; k++) { qs += s_q[k]; vs += s_v[k]; }
            if (vs > 0) {
                atomicAdd(&g_qsum, qs);
                atomicAdd(&g_vfsum, (double)vs);
            }
        }
    }
}

// ---------------- final: G/T/q_tet (block 0) + S(Q) (all); last block resets --------
__global__ void __launch_bounds__(256)
final_kernel(const float* __restrict__ rbins, const float* __restrict__ qbins,
             float* __restrict__ out, int n, int nbins, int nq) {
    __shared__ float integ2[256], integp[256], sr[256];
    __shared__ int   sLast;
    int t = threadIdx.x;
    float rho = g_rho, dr = g_dr;
    int   nSiT = g_nSiTot;
    float mb   = ((float)nSiT * B_SI + (float)(n - nSiT) * B_O) / (float)n;
    float invmb2 = __fdividef(1.0f, mb * mb);
    float gnorm  = __fdividef(invmb2, (float)n * rho * 4.0f * PI_F * dr);
    if (t < nbins) {
        float r  = rbins[t];
        float G  = (float)g_hist[t] * gnorm * __fdividef(1.0f, r * r);
        float ig = r * r * (G - 1.0f);
        integp[t] = ig;
        integ2[t] = ig * __fdividef(1.0f, r);    // integ/r, for sin(qr)/(qr)
        sr[t]     = r;
        if (blockIdx.x == 0) {
            out[t]         = G;
            out[nbins + t] = 4.0f * PI_F * rho * r * G;
        }
    }
    if (blockIdx.x == 0 && t == 0) {
        double denom = g_vfsum > 1.0 ? g_vfsum : 1.0;
        out[2 * nbins + nq] = (float)(g_qsum / denom);
    }
    __syncthreads();
    int warp = t >> 5, lane = t & 31;
    int qidx = blockIdx.x * 8 + warp;
    if (qidx < nq) {
        float q    = qbins[qidx];
        float invq = __fdividef(1.0f, q);
        float s = 0.0f;
        for (int k = lane; k < nbins; k += 32) {
            float px = q * sr[k];
            float term = (px == 0.0f) ? integp[k] : integ2[k] * __sinf(px) * invq;
            s += term;
        }
        #pragma unroll
        for (int o = 16; o > 0; o >>= 1) s += __shfl_down_sync(0xffffffffu, s, o);
        if (lane == 0) out[2 * nbins + qidx] = 1.0f + 4.0f * PI_F * rho * dr * s;
    }
    // last-arriving block resets replay-invariant accumulators
    __syncthreads();
    if (t == 0) {
        __threadfence();
        int v = atomicAdd(&g_arriveF, 1);
        sLast = (v == (int)gridDim.x - 1) ? 1 : 0;
    }
    __syncthreads();
    if (sLast) {
        if (t < 256) g_hist[t] = 0.0;
        g_cellCnt[t] = 0;
        g_cellCnt[t + 256] = 0;
        if (t == 0) {
            g_qsum = 0.0; g_vfsum = 0.0;
            g_arriveF = 0; g_nSiTot = 0; g_overflow = 0;
        }
    }
}

// ---------------- launch ------------------------------------------------------------
extern "C" void kernel_launch(void* const* d_in, const int* in_sizes, int n_in,
                              void* d_out, int out_size) {
    const float* pos     = (const float*)d_in[0];
    const float* cell    = (const float*)d_in[1];
    const float* rbins   = (const float*)d_in[2];
    const float* qbins   = (const float*)d_in[3];
    const int*   species = (const int*)  d_in[4];
    int n     = in_sizes[0] / 3;
    int nbins = in_sizes[2];
    int nq    = in_sizes[3];

    int ablocks = (n + 127) / 128;
    assign_kernel<<<ablocks, 128>>>(pos, cell, rbins, species, n, nbins);

    int tilesI = (n + 255) / 256, tilesJ = (n + 511) / 512;
    int pairBlocks = tilesI * tilesJ;
    if (pairBlocks < NCELLS) pairBlocks = NCELLS;
    int qtetBlocks = (n + 7) / 8;       // 8 warps/block; non-Si warps exit after 1 load
    main_kernel<<<pairBlocks + qtetBlocks, 256>>>(pos, species, n, nbins, pairBlocks);

    final_kernel<<<(nq + 7) / 8, 256>>>(rbins, qbins, (float*)d_out, n, nbins, nq);
}

// round 15
// speedup vs baseline: 1.0883x; 1.0883x over previous
#include <cuda_runtime.h>
#include <math.h>

#define B_SI 4.1491f
#define B_O  5.803f
#define CUTOFF 3.5f
#define PI_F 3.14159274101257324f   // (float)M_PI

#define CDIM   8
#define NCELLS 512                  // CDIM^3
#define CCAP   32                   // fixed capacity per cell
#define NMAX   8192

// ---------------- f32x2 packed helpers (sm_100+) -----------------------------------
#define PK2(out, lo, hi) asm("mov.b64 %0, {%1, %2};" : "=l"(out) : "f"(lo), "f"(hi))
#define UNPK2(lo, hi, in) asm("mov.b64 {%0, %1}, %2;" : "=f"(lo), "=f"(hi) : "l"(in))
#define ADD2(d, a, b) asm("add.rn.f32x2 %0, %1, %2;" : "=l"(d) : "l"(a), "l"(b))
#define MUL2(d, a, b) asm("mul.rn.f32x2 %0, %1, %2;" : "=l"(d) : "l"(a), "l"(b))
#define FMA2(d, a, b, c) asm("fma.rn.f32x2 %0, %1, %2, %3;" : "=l"(d) : "l"(a), "l"(b), "l"(c))

// ---------------- device globals (scratch; no allocations allowed) ----------------
__device__ float  g_inv[9];
__device__ float  g_cellm[9];
__device__ float  g_rho, g_r0, g_dr, g_rsafe;
__device__ int    g_cellokGeom;
__device__ double g_hist[256];        // zero at start; re-zeroed by final_kernel
__device__ double g_qsum, g_vfsum;    // same invariant
__device__ int    g_arriveF, g_nSi, g_nSiTot, g_overflow;

__device__ float4 g_fracA[NMAX];                 // per ORIGINAL atom (brute fallback)
__device__ float4 g_scart[NCELLS * CCAP];        // slotted cartesian (wrapped) + b
__device__ int    g_sorig[NCELLS * CCAP];
__device__ int    g_siSlot[NMAX];                // slots of Si atoms
__device__ int    g_siCell[NMAX];
__device__ int    g_cellCnt[NCELLS];             // zero at start; re-zeroed by final

// ---------------- helpers ----------------------------------------------------------
__device__ __forceinline__ void insert4(float bd2[4], int bj[4], float dd, int jj) {
    if (dd < bd2[3]) {
        #pragma unroll
        for (int k = 0; k < 4; k++) {
            if (dd < bd2[k]) {
                float td = bd2[k]; bd2[k] = dd; dd = td;
                int   tj = bj[k];  bj[k]  = jj; jj = tj;
            }
        }
    }
}

__device__ __forceinline__ void warp_merge_top4(float bd2[4], int bj[4], int lane,
                                                float seld2[4], int selj[4]) {
    const float INF = 3.402823466e38f;
    int ptr = 0;
    #pragma unroll
    for (int r = 0; r < 4; r++) {
        float mv = (ptr < 4) ? bd2[ptr] : INF;
        int   mj = (ptr < 4) ? bj[ptr]  : 0x7fffffff;
        int   ml = lane;
        #pragma unroll
        for (int o = 16; o > 0; o >>= 1) {
            float ov = __shfl_down_sync(0xffffffffu, mv, o);
            int   oj = __shfl_down_sync(0xffffffffu, mj, o);
            int   ol = __shfl_down_sync(0xffffffffu, ml, o);
            if (ov < mv || (ov == mv && oj < mj)) { mv = ov; mj = oj; ml = ol; }
        }
        mv = __shfl_sync(0xffffffffu, mv, 0);
        mj = __shfl_sync(0xffffffffu, mj, 0);
        ml = __shfl_sync(0xffffffffu, ml, 0);
        if (lane == ml) ptr++;
        seld2[r] = mv; selj[r] = mj;
    }
}

__device__ __forceinline__ void compute_inv(const float a[9], float iv[9], float* det_out) {
    float c00 = a[4]*a[8] - a[5]*a[7];
    float c01 = a[5]*a[6] - a[3]*a[8];
    float c02 = a[3]*a[7] - a[4]*a[6];
    float det = a[0]*c00 + a[1]*c01 + a[2]*c02;
    float id  = 1.0f / det;
    iv[0] = c00*id;  iv[3] = c01*id;  iv[6] = c02*id;
    iv[1] = (a[2]*a[7] - a[1]*a[8])*id;
    iv[4] = (a[0]*a[8] - a[2]*a[6])*id;
    iv[7] = (a[1]*a[6] - a[0]*a[7])*id;
    iv[2] = (a[1]*a[5] - a[2]*a[4])*id;
    iv[5] = (a[2]*a[3] - a[0]*a[5])*id;
    iv[8] = (a[0]*a[4] - a[1]*a[3])*id;
    *det_out = det;
}

// ---------------- assign: straight-line frac + direct slotted scatter ---------------
__global__ void __launch_bounds__(128)
assign_kernel(const float* __restrict__ pos, const float* __restrict__ cell,
              const float* __restrict__ rbins, const int* __restrict__ species,
              int n, int nbins) {
    __shared__ int sSiList, sSiTot, sSiBase;
    int t = threadIdx.x;
    int i = blockIdx.x * 128 + t;
    if (t == 0) { sSiList = 0; sSiTot = 0; }

    // every thread computes the inverse redundantly (no stalls on shared)
    float a[9], iv[9], det;
    #pragma unroll
    for (int k = 0; k < 9; k++) a[k] = cell[k];
    compute_inv(a, iv, &det);

    // block 0 / t0: geometric scalar prep (independent of atom pass)
    if (blockIdx.x == 0 && t == 0) {
        #pragma unroll
        for (int k = 0; k < 9; k++) { g_cellm[k] = a[k]; g_inv[k] = iv[k]; }
        float adet = fabsf(det);
        g_rho = (float)n / adet;
        float r0 = rbins[0], dr = rbins[1] - rbins[0];
        g_r0 = r0; g_dr = dr;
        float c00 = a[4]*a[8]-a[5]*a[7], c10 = a[5]*a[6]-a[3]*a[8], c20 = a[3]*a[7]-a[4]*a[6];
        float n1 = sqrtf(c00*c00 + c10*c10 + c20*c20);
        float x31x = a[7]*a[2]-a[8]*a[1], x31y = a[8]*a[0]-a[6]*a[2], x31z = a[6]*a[1]-a[7]*a[0];
        float n2 = sqrtf(x31x*x31x + x31y*x31y + x31z*x31z);
        float x12x = a[1]*a[5]-a[2]*a[4], x12y = a[2]*a[3]-a[0]*a[5], x12z = a[0]*a[4]-a[1]*a[3];
        float n3 = sqrtf(x12x*x12x + x12y*x12y + x12z*x12z);
        float pmin = fminf(adet/n1, fminf(adet/n2, adet/n3));
        float rmax = r0 + (float)(nbins - 1) * dr;
        g_cellokGeom = (rmax * (float)CDIM * 0.5f <= pmin) ? 1 : 0;
        g_rsafe = pmin / (float)CDIM;
    }
    __syncthreads();

    int mySlot = -1, myCell = 0, myListIdx = -1;
    if (i < n) {
        float px = pos[3*i], py = pos[3*i+1], pz = pos[3*i+2];
        float fx = px*iv[0] + py*iv[3] + pz*iv[6];
        float fy = px*iv[1] + py*iv[4] + pz*iv[7];
        float fz = px*iv[2] + py*iv[5] + pz*iv[8];
        fx -= floorf(fx); fy -= floorf(fy); fz -= floorf(fz);
        int cx = min((int)(fx * (float)CDIM), CDIM - 1);
        int cy = min((int)(fy * (float)CDIM), CDIM - 1);
        int cz = min((int)(fz * (float)CDIM), CDIM - 1);
        int c  = cx | (cy << 3) | (cz << 6);
        int isSi = (species[i] == 0);
        float b = isSi ? B_SI : B_O;
        float4 fr; fr.x = fx; fr.y = fy; fr.z = fz; fr.w = b;
        g_fracA[i] = fr;                    // brute-path copy
        if (isSi) atomicAdd(&sSiTot, 1);
        int rank = atomicAdd(&g_cellCnt[c], 1);
        if (rank < CCAP) {
            int s = c * CCAP + rank;
            float4 cc;
            cc.x = fr.x*a[0] + fr.y*a[3] + fr.z*a[6];
            cc.y = fr.x*a[1] + fr.y*a[4] + fr.z*a[7];
            cc.z = fr.x*a[2] + fr.y*a[5] + fr.z*a[8];
            cc.w = b;
            g_scart[s] = cc;
            g_sorig[s] = i;
            if (isSi) {
                myListIdx = atomicAdd(&sSiList, 1);
                mySlot = s; myCell = c;
            }
        } else {
            atomicExch(&g_overflow, 1);     // degenerate density -> brute path
        }
    }
    __syncthreads();
    if (t == 0) {
        if (sSiTot  > 0) atomicAdd(&g_nSiTot, sSiTot);
        sSiBase = (sSiList > 0) ? atomicAdd(&g_nSi, sSiList) : 0;
    }
    __syncthreads();
    if (myListIdx >= 0) {
        g_siSlot[sSiBase + myListIdx] = mySlot;
        g_siCell[sSiBase + myListIdx] = myCell;
    }
}

// ---------------- main: pair histogram (bx < pairBlocks) + qtet (rest) -------------
__global__ void __launch_bounds__(256)
main_kernel(const float* __restrict__ pos, const int* __restrict__ species,
            int n, int nbins, int pairBlocks) {
    int bx = blockIdx.x;
    int t  = threadIdx.x;

    if (bx < pairBlocks) {
        // ===================== pair histogram =====================
        const int cellok = g_cellokGeom && !g_overflow;
        if (cellok && bx >= NCELLS) return;

        __shared__ unsigned long long scx[128], scy[128], scz[128];
        __shared__ float  scw[256];
        __shared__ float4 sjn[512];
        __shared__ float  shist[256];
        __shared__ int    nbS[63], nbCnt[63];
        __shared__ int    nbCum[64];
        __shared__ float  shx[63], shy[63], shz[63];

        shist[t] = 0.0f;

        const float r0 = g_r0, dr = g_dr;
        const float rmax  = r0 + (float)(nbins - 1) * dr;
        const float d2max = rmax * rmax + 0.01f;
        const float invdr = 1.0f / dr;
        const float binoff = -r0 * invdr;

        if (cellok) {
            int c  = bx;
            int cx = c & 7, cy = (c >> 3) & 7, cz = c >> 6;
            if (t < 63) {
                int tt = 62 + t;                    // t=0 -> self, t>0 -> positive half
                int ox = tt % 5 - 2, oy = (tt / 5) % 5 - 2, oz = tt / 25 - 2;
                int ucx = cx + ox, ucy = cy + oy, ucz = cz + oz;
                int nc = (ucx & 7) | ((ucy & 7) << 3) | ((ucz & 7) << 6);
                nbS[t]   = nc * CCAP;
                nbCnt[t] = g_cellCnt[nc];
                float wx = (float)((ucx < 0) ? -1 : (ucx >= CDIM ? 1 : 0));
                float wy = (float)((ucy < 0) ? -1 : (ucy >= CDIM ? 1 : 0));
                float wz = (float)((ucz < 0) ? -1 : (ucz >= CDIM ? 1 : 0));
                shx[t] = wx*g_cellm[0] + wy*g_cellm[3] + wz*g_cellm[6];
                shy[t] = wx*g_cellm[1] + wy*g_cellm[4] + wz*g_cellm[7];
                shz[t] = wx*g_cellm[2] + wy*g_cellm[5] + wz*g_cellm[8];
            }
            __syncthreads();
            // warp-shuffle exclusive scan over 63 counts (lane k -> cells 2k, 2k+1)
            if (t < 32) {
                int a  = nbCnt[2*t];
                int bb = (2*t + 1 < 63) ? nbCnt[2*t + 1] : 0;
                int s  = a + bb;
                int v  = s;
                #pragma unroll
                for (int o = 1; o < 32; o <<= 1) {
                    int u = __shfl_up_sync(0xffffffffu, v, o);
                    if (t >= o) v += u;
                }
                int ex = v - s;
                nbCum[2*t] = ex;
                if (2*t + 1 < 63) nbCum[2*t + 1] = ex + a;
                if (t == 31) nbCum[63] = ex + a;    // total
            }
            __syncthreads();
            int total     = nbCum[63];
            int selfStart = nbS[0];
            int nC        = nbCnt[0];              // self count
            int nCp       = (nC + 1) >> 1;

            // stage centers as packed SoA (pad odd with far sentinel, weight 0)
            for (int p = t; p < nCp; p += 256) {
                float4 a = g_scart[selfStart + 2*p];
                float4 bb;
                if (2*p + 1 < nC) bb = g_scart[selfStart + 2*p + 1];
                else { bb.x = 1e9f; bb.y = 1e9f; bb.z = 1e9f; bb.w = 0.0f; }
                unsigned long long ux, uy, uz;
                PK2(ux, a.x, bb.x); PK2(uy, a.y, bb.y); PK2(uz, a.z, bb.z);
                scx[p] = ux; scy[p] = uy; scz[p] = uz;
                scw[2*p]     = 2.0f * a.w;
                scw[2*p + 1] = 2.0f * bb.w;
            }
            __syncthreads();

            // ---- self-cell triangle (scalar, tiny) ----
            int npairs = nC * (nC - 1) / 2;
            for (int idx = t; idx < npairs; idx += 256) {
                int gj = (int)((1.0f + sqrtf(1.0f + 8.0f * (float)idx)) * 0.5f);
                while (gj * (gj - 1) / 2 > idx) gj--;
                while ((gj + 1) * gj / 2 <= idx) gj++;
                int ii = idx - gj * (gj - 1) / 2;
                float4 pi = g_scart[selfStart + ii];
                float4 pj = g_scart[selfStart + gj];
                float dx = pi.x - pj.x, dy = pi.y - pj.y, dz = pi.z - pj.z;
                float d2 = dx*dx + dy*dy + dz*dz;
                if (d2 < d2max) {
                    float dist;
                    asm("sqrt.approx.f32 %0, %1;" : "=f"(dist) : "f"(d2));
                    float x  = fmaf(dist, invdr, binoff);
                    int   b0 = __float2int_rd(x);
                    if ((unsigned)b0 < (unsigned)(nbins - 1)) {
                        float f = x - (float)b0;
                        float w = 2.0f * pi.w * pj.w;
                        atomicAdd(&shist[b0],     w * (1.0f - f));
                        atomicAdd(&shist[b0 + 1], w * f);
                    }
                }
            }

            // ---- main loop: centers (packed) vs 62 half-neighborhood cells ----
            for (int base = nC; base < total; base += 512) {
                int lim = min(512, total - base);
                // stage chunk of neighborhood NEGATED with wrap shifts applied
                for (int k = t; k < lim; k += 256) {
                    int gj = base + k;
                    int lo = 0;
                    if (nbCum[lo + 32] <= gj) lo += 32;
                    if (nbCum[lo + 16] <= gj) lo += 16;
                    if (nbCum[lo +  8] <= gj) lo +=  8;
                    if (nbCum[lo +  4] <= gj) lo +=  4;
                    if (nbCum[lo +  2] <= gj) lo +=  2;
                    if (nbCum[lo +  1] <= gj) lo +=  1;
                    float4 p = g_scart[nbS[lo] + (gj - nbCum[lo])];
                    float4 q;
                    q.x = -(p.x + shx[lo]);
                    q.y = -(p.y + shy[lo]);
                    q.z = -(p.z + shz[lo]);
                    q.w = p.w;
                    sjn[k] = q;
                }
                __syncthreads();
                for (int k = t; k < lim; k += 256) {
                    float4 pj = sjn[k];
                    unsigned long long px2, py2, pz2;
                    PK2(px2, pj.x, pj.x);
                    PK2(py2, pj.y, pj.y);
                    PK2(pz2, pj.z, pj.z);
                    float pjw = pj.w;
                    #pragma unroll 2
                    for (int p = 0; p < nCp; p++) {
                        unsigned long long dx2, dy2, dz2, d2p;
                        ADD2(dx2, scx[p], px2);      // cen + (-pj) = cen - pj
                        ADD2(dy2, scy[p], py2);
                        ADD2(dz2, scz[p], pz2);
                        MUL2(d2p, dz2, dz2);
                        FMA2(d2p, dy2, dy2, d2p);
                        FMA2(d2p, dx2, dx2, d2p);
                        float d2lo, d2hi;
                        UNPK2(d2lo, d2hi, d2p);
                        if (d2lo < d2max) {
                            float dist;
                            asm("sqrt.approx.f32 %0, %1;" : "=f"(dist) : "f"(d2lo));
                            float x  = fmaf(dist, invdr, binoff);
                            int   b0 = __float2int_rd(x);
                            if ((unsigned)b0 < (unsigned)(nbins - 1)) {
                                float f = x - (float)b0;
                                float w = scw[2*p] * pjw;
                                atomicAdd(&shist[b0],     w * (1.0f - f));
                                atomicAdd(&shist[b0 + 1], w * f);
                            }
                        }
                        if (d2hi < d2max) {
                            float dist;
                            asm("sqrt.approx.f32 %0, %1;" : "=f"(dist) : "f"(d2hi));
                            float x  = fmaf(dist, invdr, binoff);
                            int   b0 = __float2int_rd(x);
                            if ((unsigned)b0 < (unsigned)(nbins - 1)) {
                                float f = x - (float)b0;
                                float w = scw[2*p + 1] * pjw;
                                atomicAdd(&shist[b0],     w * (1.0f - f));
                                atomicAdd(&shist[b0 + 1], w * f);
                            }
                        }
                    }
                }
                __syncthreads();
            }
        } else {
            // ---- brute fallback (general cells / degenerate) ----
            int tilesJ = (n + 511) >> 9;
            int ib = bx / tilesJ;
            int jb = bx % tilesJ;
            int iBase = ib * 256, jBase = jb * 512;
            const float c0 = g_cellm[0], c1 = g_cellm[1], c2 = g_cellm[2];
            const float c3 = g_cellm[3], c4 = g_cellm[4], c5 = g_cellm[5];
            const float c6 = g_cellm[6], c7 = g_cellm[7], c8 = g_cellm[8];
            if (iBase < n && jBase + 511 > iBase) {
                for (int k = t; k < 512; k += 256) {
                    int j = jBase + k;
                    float4 v;
                    if (j < n) v = g_fracA[j];
                    else { v.x = 1e18f; v.y = 1e18f; v.z = 1e18f; v.w = 0.0f; }
                    sjn[k] = v;
                }
                __syncthreads();
                int i = iBase + t;
                if (i < n) {
                    float4 pi = g_fracA[i];
                    int kmin = i - jBase + 1; if (kmin < 0) kmin = 0;
                    int kmax = n - jBase; if (kmax > 512) kmax = 512;
                    for (int k = kmin; k < kmax; k++) {
                        float4 pj = sjn[k];
                        float fx = pi.x - pj.x; fx -= rintf(fx);
                        float fy = pi.y - pj.y; fy -= rintf(fy);
                        float fz = pi.z - pj.z; fz -= rintf(fz);
                        float dx = fx*c0 + fy*c3 + fz*c6;
                        float dy = fx*c1 + fy*c4 + fz*c7;
                        float dz = fx*c2 + fy*c5 + fz*c8;
                        float d2 = dx*dx + dy*dy + dz*dz;
                        if (d2 < d2max) {
                            float dist = sqrtf(d2);
                            float x  = fmaf(dist, invdr, binoff);
                            int   b0 = __float2int_rd(x);
                            if ((unsigned)b0 < (unsigned)(nbins - 1)) {
                                float f = x - (float)b0;
                                float w = 2.0f * pi.w * pj.w;
                                atomicAdd(&shist[b0],     w * (1.0f - f));
                                atomicAdd(&shist[b0 + 1], w * f);
                            }
                        }
                    }
                }
                __syncthreads();
            }
        }
        __syncthreads();
        if (t < nbins && shist[t] != 0.0f) atomicAdd(&g_hist[t], (double)shist[t]);
    } else {
        // ===================== tetrahedral order parameter =====================
        int qb   = bx - pairBlocks;
        int gw   = qb * 8 + (t >> 5);
        int lane = t & 31;
        int wib  = t >> 5;

        const float i0v = g_inv[0], i1v = g_inv[1], i2v = g_inv[2];
        const float i3v = g_inv[3], i4v = g_inv[4], i5v = g_inv[5];
        const float i6v = g_inv[6], i7v = g_inv[7], i8v = g_inv[8];
        const float c0 = g_cellm[0], c1 = g_cellm[1], c2 = g_cellm[2];
        const float c3 = g_cellm[3], c4 = g_cellm[4], c5 = g_cellm[5];
        const float c6 = g_cellm[6], c7 = g_cellm[7], c8 = g_cellm[8];
        const float rsafe  = g_rsafe;
        const int   cellok = g_cellokGeom && !g_overflow;
        const float INF = 3.402823466e38f;

        float qi = 0.0f;
        int   vf = 0;

        int i = -1, slot = -1, ccell = -1;
        float4 ci = {0.f, 0.f, 0.f, 0.f};
        if (cellok) {
            if (gw < g_nSi) {
                slot  = g_siSlot[gw];
                ccell = g_siCell[gw];
                i     = g_sorig[slot];
                ci    = g_scart[slot];
            }
        } else {
            if (gw < n && species[gw] == 0) i = gw;
        }

        if (i >= 0) {
            float pix = pos[3*i], piy = pos[3*i+1], piz = pos[3*i+2];
            float seld2[4]; int selj[4];
            bool valid = false;

            if (cellok) {
                int cx = ccell & 7, cy = (ccell >> 3) & 7, cz = ccell >> 6;
                float bd2[4] = {INF, INF, INF, INF};
                int   bj [4] = {0x7fffffff, 0x7fffffff, 0x7fffffff, 0x7fffffff};
                int found = 0;
                if (lane < 27) {
                    int ox = lane % 3 - 1, oy = (lane / 3) % 3 - 1, oz = lane / 9 - 1;
                    int ucx = cx + ox, ucy = cy + oy, ucz = cz + oz;
                    int nc = (ucx & 7) | ((ucy & 7) << 3) | ((ucz & 7) << 6);
                    float wx = (float)((ucx < 0) ? -1 : (ucx >= CDIM ? 1 : 0));
                    float wy = (float)((ucy < 0) ? -1 : (ucy >= CDIM ? 1 : 0));
                    float wz = (float)((ucz < 0) ? -1 : (ucz >= CDIM ? 1 : 0));
                    float sx = wx*c0 + wy*c3 + wz*c6;
                    float sy = wx*c1 + wy*c4 + wz*c7;
                    float sz = wx*c2 + wy*c5 + wz*c8;
                    int st = nc * CCAP, en = st + g_cellCnt[nc];
                    for (int s = st; s < en; s++) {
                        float4 fj = g_scart[s];
                        if (fj.w == B_SI || s == slot) continue;
                        float dx = ci.x - (fj.x + sx);
                        float dy = ci.y - (fj.y + sy);
                        float dz = ci.z - (fj.z + sz);
                        float d2 = dx*dx + dy*dy + dz*dz;
                        found++;
                        insert4(bd2, bj, d2, g_sorig[s]);
                    }
                }
                int foundTot = __reduce_add_sync(0xffffffffu, found);
                warp_merge_top4(bd2, bj, lane, seld2, selj);
                valid = (foundTot >= 4) && (seld2[3] < rsafe * rsafe);
            }

            if (!valid) {
                // exact full-scan fallback
                float bd2[4] = {INF, INF, INF, INF};
                int   bj [4] = {0x7fffffff, 0x7fffffff, 0x7fffffff, 0x7fffffff};
                for (int j = lane; j < n; j += 32) {
                    if (j == i || species[j] == 0) continue;
                    float dx0 = pix - pos[3*j];
                    float dy0 = piy - pos[3*j+1];
                    float dz0 = piz - pos[3*j+2];
                    float fx = dx0*i0v + dy0*i3v + dz0*i6v;
                    float fy = dx0*i1v + dy0*i4v + dz0*i7v;
                    float fz = dx0*i2v + dy0*i5v + dz0*i8v;
                    fx -= rintf(fx); fy -= rintf(fy); fz -= rintf(fz);
                    float dx = fx*c0 + fy*c3 + fz*c6;
                    float dy = fx*c1 + fy*c4 + fz*c7;
                    float dz = fx*c2 + fy*c5 + fz*c8;
                    float d2 = dx*dx + dy*dy + dz*dz;
                    insert4(bd2, bj, d2, j);
                }
                warp_merge_top4(bd2, bj, lane, seld2, selj);
            }

            if (lane == 0 && selj[3] < n) {
                float ux[4], uy[4], uz[4], dmax = 0.0f;
                #pragma unroll
                for (int k = 0; k < 4; k++) {
                    int j = selj[k];
                    float dx0 = pix - pos[3*j];
                    float dy0 = piy - pos[3*j+1];
                    float dz0 = piz - pos[3*j+2];
                    float fx = dx0*i0v + dy0*i3v + dz0*i6v;
                    float fy = dx0*i1v + dy0*i4v + dz0*i7v;
                    float fz = dx0*i2v + dy0*i5v + dz0*i8v;
                    fx -= rintf(fx); fy -= rintf(fy); fz -= rintf(fz);
                    float dx = fx*c0 + fy*c3 + fz*c6;
                    float dy = fx*c1 + fy*c4 + fz*c7;
                    float dz = fx*c2 + fy*c5 + fz*c8;
                    float dist = sqrtf(seld2[k]);
                    dmax = fmaxf(dmax, dist);
                    ux[k] = dx / dist; uy[k] = dy / dist; uz[k] = dz / dist;
                }
                float s = 0.0f;
                #pragma unroll
                for (int k = 0; k < 4; k++)
                    #pragma unroll
                    for (int l = k + 1; l < 4; l++) {
                        float cc = ux[k]*ux[l] + uy[k]*uy[l] + uz[k]*uz[l];
                        float tt = cc + (1.0f / 3.0f);
                        s += tt * tt;
                    }
                if (dmax < CUTOFF) { qi = 1.0f - 0.375f * s; vf = 1; }
            }
        }

        __shared__ double s_q[8];
        __shared__ int    s_v[8];
        if (lane == 0) { s_q[wib] = (double)qi; s_v[wib] = vf; }
        __syncthreads();
        if (t == 0) {
            double qs = 0.0; int vs = 0;
            #pragma unroll
            for (int k = 0; k < 8; k++) { qs += s_q[k]; vs += s_v[k]; }
            if (vs > 0) {
                atomicAdd(&g_qsum, qs);
                atomicAdd(&g_vfsum, (double)vs);
            }
        }
    }
}

// ---------------- final: G/T/q_tet (block 0) + S(Q) (all); last block resets --------
__global__ void __launch_bounds__(512)
final_kernel(const float* __restrict__ rbins, const float* __restrict__ qbins,
             float* __restrict__ out, int n, int nbins, int nq) {
    __shared__ float integ2[256], integp[256], sr[256];
    __shared__ int   sLast;
    int t = threadIdx.x;
    float rho = g_rho, dr = g_dr;
    int   nSiT = g_nSiTot;
    float mb   = ((float)nSiT * B_SI + (float)(n - nSiT) * B_O) / (float)n;
    float invmb2 = __fdividef(1.0f, mb * mb);
    float gnorm  = __fdividef(invmb2, (float)n * rho * 4.0f * PI_F * dr);
    if (t < nbins) {
        float r  = rbins[t];
        float G  = (float)g_hist[t] * gnorm * __fdividef(1.0f, r * r);
        float ig = r * r * (G - 1.0f);
        integp[t] = ig;
        integ2[t] = ig * __fdividef(1.0f, r);    // integ/r, for sin(qr)/(qr)
        sr[t]     = r;
        if (blockIdx.x == 0) {
            out[t]         = G;
            out[nbins + t] = 4.0f * PI_F * rho * r * G;
        }
    }
    if (blockIdx.x == 0 && t == 0) {
        double denom = g_vfsum > 1.0 ? g_vfsum : 1.0;
        out[2 * nbins + nq] = (float)(g_qsum / denom);
    }
    __syncthreads();
    int warp = t >> 5, lane = t & 31;
    int qidx = blockIdx.x * 16 + warp;            // 16 warps per 512-thread block
    if (qidx < nq) {
        float q    = qbins[qidx];
        float invq = __fdividef(1.0f, q);
        float s = 0.0f;
        for (int k = lane; k < nbins; k += 32) {
            float px = q * sr[k];
            float term = (px == 0.0f) ? integp[k] : integ2[k] * __sinf(px) * invq;
            s += term;
        }
        #pragma unroll
        for (int o = 16; o > 0; o >>= 1) s += __shfl_down_sync(0xffffffffu, s, o);
        if (lane == 0) out[2 * nbins + qidx] = 1.0f + 4.0f * PI_F * rho * dr * s;
    }
    // last-arriving block resets replay-invariant accumulators
    __syncthreads();
    if (t == 0) {
        __threadfence();
        int v = atomicAdd(&g_arriveF, 1);
        sLast = (v == (int)gridDim.x - 1) ? 1 : 0;
    }
    __syncthreads();
    if (sLast && t < 256) {
        g_hist[t] = 0.0;
        g_cellCnt[t] = 0;
        g_cellCnt[t + 256] = 0;
        if (t == 0) {
            g_qsum = 0.0; g_vfsum = 0.0;
            g_arriveF = 0; g_nSi = 0; g_nSiTot = 0; g_overflow = 0;
        }
    }
}

// ---------------- launch ------------------------------------------------------------
extern "C" void kernel_launch(void* const* d_in, const int* in_sizes, int n_in,
                              void* d_out, int out_size) {
    const float* pos     = (const float*)d_in[0];
    const float* cell    = (const float*)d_in[1];
    const float* rbins   = (const float*)d_in[2];
    const float* qbins   = (const float*)d_in[3];
    const int*   species = (const int*)  d_in[4];
    int n     = in_sizes[0] / 3;
    int nbins = in_sizes[2];
    int nq    = in_sizes[3];

    int ablocks = (n + 127) / 128;
    assign_kernel<<<ablocks, 128>>>(pos, cell, rbins, species, n, nbins);

    int tilesI = (n + 255) / 256, tilesJ = (n + 511) / 512;
    int pairBlocks = tilesI * tilesJ;
    if (pairBlocks < NCELLS) pairBlocks = NCELLS;
    int qtetBlocks = (n + 7) / 8;       // 8 warps/block; extra warps exit early
    main_kernel<<<pairBlocks + qtetBlocks, 256>>>(pos, species, n, nbins, pairBlocks);

    final_kernel<<<(nq + 15) / 16, 512>>>(rbins, qbins, (float*)d_out, n, nbins, nq);
}